// round 3
// baseline (speedup 1.0000x reference)
#include <cuda_runtime.h>
#include <math.h>

#define Nn 50000
#define Ee 1600000
#define Ff 128
#define Ll 3
#define Gg 128
#define Cc 10
#define BN_EPS 1e-5f

#define TILE_M 32
#define MLP_THREADS 256
#define MLP_SMEM ((2*128*128 + 2*TILE_M*128) * 4)   // 163840 bytes

// scratch (device globals — no allocation allowed). 256B-aligned for float4 /
// red.global.add.v4.f32 access.
__device__ __align__(256) float g_agg[(size_t)Nn * Ff];
__device__ __align__(256) float g_x1[(size_t)Nn * Ff];
__device__ __align__(256) float g_x2[(size_t)Nn * Ff];
__device__ __align__(256) float g_pool[Gg * Ff];
__device__ __align__(256) float g_cnt[Gg];

// ---------------------------------------------------------------------------
// agg = x  (so that h = x + sum_in becomes: init agg with x, then scatter-add)
__global__ void copy_kernel(const float* __restrict__ src, float* __restrict__ dst, int n4) {
    int i = blockIdx.x * blockDim.x + threadIdx.x;
    if (i < n4) ((float4*)dst)[i] = ((const float4*)src)[i];
}

// ---------------------------------------------------------------------------
// one warp per edge: lane handles 4 floats; vector RED into agg[dst]
// NOTE: edge_index is int32 (JAX x64 disabled downcasts int64 -> int32).
__global__ void scatter_kernel(const float* __restrict__ x,
                               const int* __restrict__ ei,
                               float* __restrict__ agg) {
    int gid  = blockIdx.x * blockDim.x + threadIdx.x;
    int e    = gid >> 5;
    int lane = gid & 31;
    if (e >= Ee) return;
    int s = ei[e];
    int d = ei[Ee + e];
    float4 v = *(const float4*)(x + (size_t)s * Ff + lane * 4);
    float* p = agg + (size_t)d * Ff + lane * 4;
    asm volatile("red.global.add.v4.f32 [%0], {%1,%2,%3,%4};"
                 :: "l"(p), "f"(v.x), "f"(v.y), "f"(v.z), "f"(v.w) : "memory");
}

// ---------------------------------------------------------------------------
// fused MLP: xout = relu(BN(relu(agg@W1 + b1)@W2 + b2))
// CTA: 256 threads, 32-node tile, W1/W2 staged in smem.
__global__ void mlp_kernel(const float* __restrict__ agg,
                           const float* __restrict__ W1, const float* __restrict__ b1,
                           const float* __restrict__ W2, const float* __restrict__ b2,
                           const float* __restrict__ gamma, const float* __restrict__ beta,
                           const float* __restrict__ rmean, const float* __restrict__ rvar,
                           float* __restrict__ xout) {
    extern __shared__ float sm[];
    float* sW1 = sm;                       // 128*128
    float* sW2 = sm + 128 * 128;           // 128*128
    float* sH  = sm + 2 * 128 * 128;       // 32*128
    float* sM  = sH + TILE_M * 128;        // 32*128

    int t = threadIdx.x;
    int row0 = blockIdx.x * TILE_M;

    // stage weights (float4, coalesced)
    #pragma unroll
    for (int i = t; i < (128 * 128) / 4; i += MLP_THREADS) {
        ((float4*)sW1)[i] = ((const float4*)W1)[i];
        ((float4*)sW2)[i] = ((const float4*)W2)[i];
    }
    // stage input tile
    for (int i = t; i < (TILE_M * 128) / 4; i += MLP_THREADS) {
        int r = i >> 5;  // 32 float4s per row
        if (row0 + r < Nn)
            ((float4*)sH)[i] = ((const float4*)agg)[(size_t)row0 * 32 + i];
        else
            ((float4*)sH)[i] = make_float4(0.f, 0.f, 0.f, 0.f);
    }
    __syncthreads();

    int tx = t & 31;   // col group: cols tx*4 .. tx*4+3
    int ty = t >> 5;   // row group: rows ty*4 .. ty*4+3  (warp == fixed ty -> sH broadcast)

    // ---- GEMM1: M = relu(H @ W1 + b1) ----
    float acc[4][4];
    #pragma unroll
    for (int r = 0; r < 4; r++)
        #pragma unroll
        for (int c = 0; c < 4; c++) acc[r][c] = 0.f;

    #pragma unroll 4
    for (int k = 0; k < 128; k++) {
        float4 w = ((const float4*)(sW1 + k * 128))[tx];
        #pragma unroll
        for (int r = 0; r < 4; r++) {
            float h = sH[(ty * 4 + r) * 128 + k];
            acc[r][0] += h * w.x; acc[r][1] += h * w.y;
            acc[r][2] += h * w.z; acc[r][3] += h * w.w;
        }
    }
    {
        float4 bb = ((const float4*)b1)[tx];
        #pragma unroll
        for (int r = 0; r < 4; r++) {
            float4 v;
            v.x = fmaxf(acc[r][0] + bb.x, 0.f);
            v.y = fmaxf(acc[r][1] + bb.y, 0.f);
            v.z = fmaxf(acc[r][2] + bb.z, 0.f);
            v.w = fmaxf(acc[r][3] + bb.w, 0.f);
            ((float4*)(sM + (ty * 4 + r) * 128))[tx] = v;
        }
    }
    __syncthreads();

    // ---- GEMM2: out = relu(BN(M @ W2 + b2)) ----
    #pragma unroll
    for (int r = 0; r < 4; r++)
        #pragma unroll
        for (int c = 0; c < 4; c++) acc[r][c] = 0.f;

    #pragma unroll 4
    for (int k = 0; k < 128; k++) {
        float4 w = ((const float4*)(sW2 + k * 128))[tx];
        #pragma unroll
        for (int r = 0; r < 4; r++) {
            float h = sM[(ty * 4 + r) * 128 + k];
            acc[r][0] += h * w.x; acc[r][1] += h * w.y;
            acc[r][2] += h * w.z; acc[r][3] += h * w.w;
        }
    }
    {
        float4 bb = ((const float4*)b2)[tx];
        float4 gm = ((const float4*)gamma)[tx];
        float4 bt = ((const float4*)beta)[tx];
        float4 rm = ((const float4*)rmean)[tx];
        float4 rv = ((const float4*)rvar)[tx];
        float4 is;
        is.x = rsqrtf(rv.x + BN_EPS); is.y = rsqrtf(rv.y + BN_EPS);
        is.z = rsqrtf(rv.z + BN_EPS); is.w = rsqrtf(rv.w + BN_EPS);
        #pragma unroll
        for (int r = 0; r < 4; r++) {
            int row = row0 + ty * 4 + r;
            if (row < Nn) {
                float4 v;
                v.x = fmaxf((acc[r][0] + bb.x - rm.x) * is.x * gm.x + bt.x, 0.f);
                v.y = fmaxf((acc[r][1] + bb.y - rm.y) * is.y * gm.y + bt.y, 0.f);
                v.z = fmaxf((acc[r][2] + bb.z - rm.z) * is.z * gm.z + bt.z, 0.f);
                v.w = fmaxf((acc[r][3] + bb.w - rm.w) * is.w * gm.w + bt.w, 0.f);
                ((float4*)(xout + (size_t)row * 128))[tx] = v;
            }
        }
    }
}

// ---------------------------------------------------------------------------
__global__ void zero_pool_kernel(float* __restrict__ pool, float* __restrict__ cnt) {
    int i = blockIdx.x * blockDim.x + threadIdx.x;
    if (i < Gg * Ff) pool[i] = 0.f;
    if (i < Gg) cnt[i] = 0.f;
}

// one warp per node; vector RED into pooled[batch[node]]
// NOTE: batch is int32 (JAX x64 disabled).
__global__ void pool_kernel(const float* __restrict__ x,
                            const int* __restrict__ batch,
                            float* __restrict__ pool, float* __restrict__ cnt) {
    int gid  = blockIdx.x * blockDim.x + threadIdx.x;
    int node = gid >> 5;
    int lane = gid & 31;
    if (node >= Nn) return;
    int g = batch[node];
    float4 v = *(const float4*)(x + (size_t)node * Ff + lane * 4);
    float* p = pool + g * Ff + lane * 4;
    asm volatile("red.global.add.v4.f32 [%0], {%1,%2,%3,%4};"
                 :: "l"(p), "f"(v.x), "f"(v.y), "f"(v.z), "f"(v.w) : "memory");
    if (lane == 0) atomicAdd(&cnt[g], 1.0f);
}

// ---------------------------------------------------------------------------
__global__ void final_kernel(const float* __restrict__ pool, const float* __restrict__ cnt,
                             const float* __restrict__ fc_w, const float* __restrict__ fc_b,
                             float* __restrict__ out) {
    int g = threadIdx.x;
    if (g >= Gg) return;
    float inv = 1.0f / fmaxf(cnt[g], 1.0f);
    float logits[Cc];
    #pragma unroll
    for (int j = 0; j < Cc; j++) logits[j] = fc_b[j];
    for (int k = 0; k < Ff; k++) {
        float p = pool[g * Ff + k] * inv;
        #pragma unroll
        for (int j = 0; j < Cc; j++) logits[j] += p * fc_w[k * Cc + j];
    }
    float m = logits[0];
    #pragma unroll
    for (int j = 1; j < Cc; j++) m = fmaxf(m, logits[j]);
    float s = 0.f;
    #pragma unroll
    for (int j = 0; j < Cc; j++) s += expf(logits[j] - m);
    float ls = logf(s) + m;
    #pragma unroll
    for (int j = 0; j < Cc; j++) out[g * Cc + j] = logits[j] - ls;
}

// ---------------------------------------------------------------------------
extern "C" void kernel_launch(void* const* d_in, const int* in_sizes, int n_in,
                              void* d_out, int out_size) {
    const float* x     = (const float*)d_in[0];
    const int*   ei    = (const int*)d_in[1];     // int32 indices
    const int*   batch = (const int*)d_in[2];     // int32 indices
    const float* W1    = (const float*)d_in[3];
    const float* b1    = (const float*)d_in[4];
    const float* W2    = (const float*)d_in[5];
    const float* b2    = (const float*)d_in[6];
    const float* gamma = (const float*)d_in[7];
    const float* beta  = (const float*)d_in[8];
    const float* rmean = (const float*)d_in[9];
    const float* rvar  = (const float*)d_in[10];
    const float* fc_w  = (const float*)d_in[11];
    const float* fc_b  = (const float*)d_in[12];
    float* out = (float*)d_out;

    cudaFuncSetAttribute(mlp_kernel, cudaFuncAttributeMaxDynamicSharedMemorySize, MLP_SMEM);

    float *agg, *x1, *x2, *pool, *cnt;
    cudaGetSymbolAddress((void**)&agg,  g_agg);
    cudaGetSymbolAddress((void**)&x1,   g_x1);
    cudaGetSymbolAddress((void**)&x2,   g_x2);
    cudaGetSymbolAddress((void**)&pool, g_pool);
    cudaGetSymbolAddress((void**)&cnt,  g_cnt);

    const int n4 = Nn * Ff / 4;
    const int copy_blocks    = (n4 + 255) / 256;
    const int scatter_blocks = (Ee * 32 + 255) / 256;
    const int mlp_blocks     = (Nn + TILE_M - 1) / TILE_M;
    const int pool_blocks    = (Nn * 32 + 255) / 256;

    const float* cur = x;
    float* outs[Ll] = { x1, x2, x1 };
    for (int l = 0; l < Ll; l++) {
        copy_kernel<<<copy_blocks, 256>>>(cur, agg, n4);
        scatter_kernel<<<scatter_blocks, 256>>>(cur, ei, agg);
        mlp_kernel<<<mlp_blocks, MLP_THREADS, MLP_SMEM>>>(
            agg,
            W1 + (size_t)l * 128 * 128, b1 + (size_t)l * 128,
            W2 + (size_t)l * 128 * 128, b2 + (size_t)l * 128,
            gamma + (size_t)l * 128, beta + (size_t)l * 128,
            rmean + (size_t)l * 128, rvar + (size_t)l * 128,
            outs[l]);
        cur = outs[l];
    }

    zero_pool_kernel<<<(Gg * Ff + 255) / 256, 256>>>(pool, cnt);
    pool_kernel<<<pool_blocks, 256>>>(cur, batch, pool, cnt);
    final_kernel<<<1, 128>>>(pool, cnt, fc_w, fc_b, out);
}

// round 4
// speedup vs baseline: 1.5145x; 1.5145x over previous
#include <cuda_runtime.h>
#include <math.h>

#define Nn 50000
#define Ee 1600000
#define Ff 128
#define Ll 3
#define Gg 128
#define Cc 10
#define BN_EPS 1e-5f

#define TILE_M 32
#define MLP_THREADS 256
#define MLP_SMEM ((2*128*128 + 2*TILE_M*128) * 4)   // 163840 bytes

// scratch (device globals — no allocation allowed)
__device__ __align__(256) float g_agg[(size_t)Nn * Ff];
__device__ __align__(256) float g_x1[(size_t)Nn * Ff];
__device__ __align__(256) float g_x2[(size_t)Nn * Ff];
__device__ __align__(256) float g_pool[Gg * Ff];
__device__ __align__(256) float g_cnt[Gg];
// CSR scratch
__device__ __align__(256) int g_deg[Nn];
__device__ __align__(256) int g_rowptr[Nn + 1];
__device__ __align__(256) int g_cursor[Nn];
__device__ __align__(256) int g_srcs[Ee];

// ---------------------------------------------------------------------------
__global__ void zero_deg_kernel(int* __restrict__ deg) {
    int i = blockIdx.x * blockDim.x + threadIdx.x;
    if (i < Nn) deg[i] = 0;
}

// degree histogram over dst
__global__ void count_kernel(const int* __restrict__ ei, int* __restrict__ deg) {
    int e = blockIdx.x * blockDim.x + threadIdx.x;
    if (e < Ee) atomicAdd(&deg[ei[Ee + e]], 1);
}

// single-block exclusive scan over deg -> rowptr, cursor (warp-shuffle scan)
__global__ void scan_kernel(const int* __restrict__ deg,
                            int* __restrict__ rowptr, int* __restrict__ cursor) {
    __shared__ int wsum[32];
    __shared__ int s_carry;
    int t = threadIdx.x;              // 1024 threads
    int lane = t & 31, wid = t >> 5;
    if (t == 0) s_carry = 0;
    __syncthreads();
    for (int base = 0; base < Nn; base += 1024) {
        int idx = base + t;
        int v = (idx < Nn) ? deg[idx] : 0;
        // warp inclusive scan
        int inc = v;
        #pragma unroll
        for (int d = 1; d < 32; d <<= 1) {
            int o = __shfl_up_sync(0xffffffffu, inc, d);
            if (lane >= d) inc += o;
        }
        if (lane == 31) wsum[wid] = inc;
        __syncthreads();
        if (wid == 0) {
            int wv = (lane < 32) ? wsum[lane] : 0;
            int winc = wv;
            #pragma unroll
            for (int d = 1; d < 32; d <<= 1) {
                int o = __shfl_up_sync(0xffffffffu, winc, d);
                if (lane >= d) winc += o;
            }
            wsum[lane] = winc - wv;   // exclusive warp offsets
        }
        __syncthreads();
        int excl = s_carry + wsum[wid] + inc - v;
        if (idx < Nn) { rowptr[idx] = excl; cursor[idx] = excl; }
        __syncthreads();
        if (t == 1023) s_carry += wsum[31] + inc;  // wsum[31] is exclusive offset of warp 31
        __syncthreads();
    }
    if (t == 0) rowptr[Nn] = s_carry;
}

// scatter edge srcs into CSR slots
__global__ void fill_kernel(const int* __restrict__ ei,
                            int* __restrict__ cursor, int* __restrict__ srcs) {
    int e = blockIdx.x * blockDim.x + threadIdx.x;
    if (e >= Ee) return;
    int s = ei[e];
    int d = ei[Ee + e];
    int slot = atomicAdd(&cursor[d], 1);
    srcs[slot] = s;
}

// ---------------------------------------------------------------------------
// one warp per node: agg[node] = x[node] + sum_{s in in(node)} x[s]
__global__ void gather_kernel(const float* __restrict__ x,
                              const int* __restrict__ rowptr,
                              const int* __restrict__ srcs,
                              float* __restrict__ agg) {
    int gid  = blockIdx.x * blockDim.x + threadIdx.x;
    int node = gid >> 5;
    int lane = gid & 31;
    if (node >= Nn) return;
    int beg = rowptr[node], end = rowptr[node + 1];
    const float* xb = x + lane * 4;
    float4 acc = *(const float4*)(xb + (size_t)node * Ff);
    for (int e0 = beg; e0 < end; e0 += 32) {
        int my = (e0 + lane < end) ? srcs[e0 + lane] : -1;
        int cnt = min(end - e0, 32);
        #pragma unroll 4
        for (int j = 0; j < cnt; j++) {
            int s = __shfl_sync(0xffffffffu, my, j);
            float4 v = *(const float4*)(xb + (size_t)s * Ff);
            acc.x += v.x; acc.y += v.y; acc.z += v.z; acc.w += v.w;
        }
    }
    *(float4*)(agg + (size_t)node * Ff + lane * 4) = acc;
}

// ---------------------------------------------------------------------------
// fused MLP: xout = relu(BN(relu(agg@W1 + b1)@W2 + b2))
__global__ void mlp_kernel(const float* __restrict__ agg,
                           const float* __restrict__ W1, const float* __restrict__ b1,
                           const float* __restrict__ W2, const float* __restrict__ b2,
                           const float* __restrict__ gamma, const float* __restrict__ beta,
                           const float* __restrict__ rmean, const float* __restrict__ rvar,
                           float* __restrict__ xout) {
    extern __shared__ float sm[];
    float* sW1 = sm;                       // 128*128
    float* sW2 = sm + 128 * 128;           // 128*128
    float* sH  = sm + 2 * 128 * 128;       // 32*128
    float* sM  = sH + TILE_M * 128;        // 32*128

    int t = threadIdx.x;
    int row0 = blockIdx.x * TILE_M;

    #pragma unroll
    for (int i = t; i < (128 * 128) / 4; i += MLP_THREADS) {
        ((float4*)sW1)[i] = ((const float4*)W1)[i];
        ((float4*)sW2)[i] = ((const float4*)W2)[i];
    }
    for (int i = t; i < (TILE_M * 128) / 4; i += MLP_THREADS) {
        int r = i >> 5;
        if (row0 + r < Nn)
            ((float4*)sH)[i] = ((const float4*)agg)[(size_t)row0 * 32 + i];
        else
            ((float4*)sH)[i] = make_float4(0.f, 0.f, 0.f, 0.f);
    }
    __syncthreads();

    int tx = t & 31;   // cols tx*4 .. tx*4+3
    int ty = t >> 5;   // rows ty*4 .. ty*4+3 (warp-uniform -> sH broadcast)

    float acc[4][4];
    #pragma unroll
    for (int r = 0; r < 4; r++)
        #pragma unroll
        for (int c = 0; c < 4; c++) acc[r][c] = 0.f;

    // ---- GEMM1: sM = relu(sH @ W1 + b1) ---- (float4 h loads)
    #pragma unroll 4
    for (int kc = 0; kc < 32; kc++) {
        float4 h[4];
        #pragma unroll
        for (int r = 0; r < 4; r++)
            h[r] = ((const float4*)(sH + (ty * 4 + r) * 128))[kc];
        #pragma unroll
        for (int kk = 0; kk < 4; kk++) {
            float4 w = ((const float4*)(sW1 + (kc * 4 + kk) * 128))[tx];
            #pragma unroll
            for (int r = 0; r < 4; r++) {
                float hv = ((const float*)&h[r])[kk];
                acc[r][0] += hv * w.x; acc[r][1] += hv * w.y;
                acc[r][2] += hv * w.z; acc[r][3] += hv * w.w;
            }
        }
    }
    {
        float4 bb = ((const float4*)b1)[tx];
        #pragma unroll
        for (int r = 0; r < 4; r++) {
            float4 v;
            v.x = fmaxf(acc[r][0] + bb.x, 0.f);
            v.y = fmaxf(acc[r][1] + bb.y, 0.f);
            v.z = fmaxf(acc[r][2] + bb.z, 0.f);
            v.w = fmaxf(acc[r][3] + bb.w, 0.f);
            ((float4*)(sM + (ty * 4 + r) * 128))[tx] = v;
        }
    }
    __syncthreads();

    // ---- GEMM2 + BN + ReLU ----
    #pragma unroll
    for (int r = 0; r < 4; r++)
        #pragma unroll
        for (int c = 0; c < 4; c++) acc[r][c] = 0.f;

    #pragma unroll 4
    for (int kc = 0; kc < 32; kc++) {
        float4 h[4];
        #pragma unroll
        for (int r = 0; r < 4; r++)
            h[r] = ((const float4*)(sM + (ty * 4 + r) * 128))[kc];
        #pragma unroll
        for (int kk = 0; kk < 4; kk++) {
            float4 w = ((const float4*)(sW2 + (kc * 4 + kk) * 128))[tx];
            #pragma unroll
            for (int r = 0; r < 4; r++) {
                float hv = ((const float*)&h[r])[kk];
                acc[r][0] += hv * w.x; acc[r][1] += hv * w.y;
                acc[r][2] += hv * w.z; acc[r][3] += hv * w.w;
            }
        }
    }
    {
        float4 bb = ((const float4*)b2)[tx];
        float4 gm = ((const float4*)gamma)[tx];
        float4 bt = ((const float4*)beta)[tx];
        float4 rm = ((const float4*)rmean)[tx];
        float4 rv = ((const float4*)rvar)[tx];
        float4 is;
        is.x = rsqrtf(rv.x + BN_EPS); is.y = rsqrtf(rv.y + BN_EPS);
        is.z = rsqrtf(rv.z + BN_EPS); is.w = rsqrtf(rv.w + BN_EPS);
        #pragma unroll
        for (int r = 0; r < 4; r++) {
            int row = row0 + ty * 4 + r;
            if (row < Nn) {
                float4 v;
                v.x = fmaxf((acc[r][0] + bb.x - rm.x) * is.x * gm.x + bt.x, 0.f);
                v.y = fmaxf((acc[r][1] + bb.y - rm.y) * is.y * gm.y + bt.y, 0.f);
                v.z = fmaxf((acc[r][2] + bb.z - rm.z) * is.z * gm.z + bt.z, 0.f);
                v.w = fmaxf((acc[r][3] + bb.w - rm.w) * is.w * gm.w + bt.w, 0.f);
                ((float4*)(xout + (size_t)row * 128))[tx] = v;
            }
        }
    }
}

// ---------------------------------------------------------------------------
__global__ void zero_pool_kernel(float* __restrict__ pool, float* __restrict__ cnt) {
    int i = blockIdx.x * blockDim.x + threadIdx.x;
    if (i < Gg * Ff) pool[i] = 0.f;
    if (i < Gg) cnt[i] = 0.f;
}

__global__ void pool_kernel(const float* __restrict__ x,
                            const int* __restrict__ batch,
                            float* __restrict__ pool, float* __restrict__ cnt) {
    int gid  = blockIdx.x * blockDim.x + threadIdx.x;
    int node = gid >> 5;
    int lane = gid & 31;
    if (node >= Nn) return;
    int g = batch[node];
    float4 v = *(const float4*)(x + (size_t)node * Ff + lane * 4);
    float* p = pool + g * Ff + lane * 4;
    asm volatile("red.global.add.v4.f32 [%0], {%1,%2,%3,%4};"
                 :: "l"(p), "f"(v.x), "f"(v.y), "f"(v.z), "f"(v.w) : "memory");
    if (lane == 0) atomicAdd(&cnt[g], 1.0f);
}

// ---------------------------------------------------------------------------
__global__ void final_kernel(const float* __restrict__ pool, const float* __restrict__ cnt,
                             const float* __restrict__ fc_w, const float* __restrict__ fc_b,
                             float* __restrict__ out) {
    int g = threadIdx.x;
    if (g >= Gg) return;
    float inv = 1.0f / fmaxf(cnt[g], 1.0f);
    float logits[Cc];
    #pragma unroll
    for (int j = 0; j < Cc; j++) logits[j] = fc_b[j];
    for (int k = 0; k < Ff; k++) {
        float p = pool[g * Ff + k] * inv;
        #pragma unroll
        for (int j = 0; j < Cc; j++) logits[j] += p * fc_w[k * Cc + j];
    }
    float m = logits[0];
    #pragma unroll
    for (int j = 1; j < Cc; j++) m = fmaxf(m, logits[j]);
    float s = 0.f;
    #pragma unroll
    for (int j = 0; j < Cc; j++) s += expf(logits[j] - m);
    float ls = logf(s) + m;
    #pragma unroll
    for (int j = 0; j < Cc; j++) out[g * Cc + j] = logits[j] - ls;
}

// ---------------------------------------------------------------------------
extern "C" void kernel_launch(void* const* d_in, const int* in_sizes, int n_in,
                              void* d_out, int out_size) {
    const float* x     = (const float*)d_in[0];
    const int*   ei    = (const int*)d_in[1];     // int32 indices
    const int*   batch = (const int*)d_in[2];     // int32 indices
    const float* W1    = (const float*)d_in[3];
    const float* b1    = (const float*)d_in[4];
    const float* W2    = (const float*)d_in[5];
    const float* b2    = (const float*)d_in[6];
    const float* gamma = (const float*)d_in[7];
    const float* beta  = (const float*)d_in[8];
    const float* rmean = (const float*)d_in[9];
    const float* rvar  = (const float*)d_in[10];
    const float* fc_w  = (const float*)d_in[11];
    const float* fc_b  = (const float*)d_in[12];
    float* out = (float*)d_out;

    cudaFuncSetAttribute(mlp_kernel, cudaFuncAttributeMaxDynamicSharedMemorySize, MLP_SMEM);

    float *agg, *x1, *x2, *pool, *cnt;
    int *deg, *rowptr, *cursor, *srcs;
    cudaGetSymbolAddress((void**)&agg,    g_agg);
    cudaGetSymbolAddress((void**)&x1,     g_x1);
    cudaGetSymbolAddress((void**)&x2,     g_x2);
    cudaGetSymbolAddress((void**)&pool,   g_pool);
    cudaGetSymbolAddress((void**)&cnt,    g_cnt);
    cudaGetSymbolAddress((void**)&deg,    g_deg);
    cudaGetSymbolAddress((void**)&rowptr, g_rowptr);
    cudaGetSymbolAddress((void**)&cursor, g_cursor);
    cudaGetSymbolAddress((void**)&srcs,   g_srcs);

    const int mlp_blocks    = (Nn + TILE_M - 1) / TILE_M;
    const int gather_blocks = (Nn * 32 + 255) / 256;
    const int pool_blocks   = (Nn * 32 + 255) / 256;

    // build CSR (dst-sorted) once per launch
    zero_deg_kernel<<<(Nn + 255) / 256, 256>>>(deg);
    count_kernel<<<(Ee + 255) / 256, 256>>>(ei, deg);
    scan_kernel<<<1, 1024>>>(deg, rowptr, cursor);
    fill_kernel<<<(Ee + 255) / 256, 256>>>(ei, cursor, srcs);

    const float* cur = x;
    float* outs[Ll] = { x1, x2, x1 };
    for (int l = 0; l < Ll; l++) {
        gather_kernel<<<gather_blocks, 256>>>(cur, rowptr, srcs, agg);
        mlp_kernel<<<mlp_blocks, MLP_THREADS, MLP_SMEM>>>(
            agg,
            W1 + (size_t)l * 128 * 128, b1 + (size_t)l * 128,
            W2 + (size_t)l * 128 * 128, b2 + (size_t)l * 128,
            gamma + (size_t)l * 128, beta + (size_t)l * 128,
            rmean + (size_t)l * 128, rvar + (size_t)l * 128,
            outs[l]);
        cur = outs[l];
    }

    zero_pool_kernel<<<(Gg * Ff + 255) / 256, 256>>>(pool, cnt);
    pool_kernel<<<pool_blocks, 256>>>(cur, batch, pool, cnt);
    final_kernel<<<1, 128>>>(pool, cnt, fc_w, fc_b, out);
}

// round 5
// speedup vs baseline: 1.6197x; 1.0695x over previous
#include <cuda_runtime.h>
#include <math.h>

#define Nn 50000
#define Ee 1600000
#define Ff 128
#define Ll 3
#define Gg 128
#define Cc 10
#define BN_EPS 1e-5f

#define TILE_M 64
#define MLP_THREADS 512
#define MLP_SMEM ((2*128*128 + TILE_M*128) * 4)   // 128KB weights + 32KB tile = 163840B

// scratch (device globals — no allocation allowed)
__device__ __align__(256) float g_agg[(size_t)Nn * Ff];
__device__ __align__(256) float g_x1[(size_t)Nn * Ff];
__device__ __align__(256) float g_x2[(size_t)Nn * Ff];
__device__ __align__(256) float g_pool[Gg * Ff];
__device__ __align__(256) float g_cnt[Gg];
// CSR scratch
__device__ __align__(256) int g_deg[Nn];
__device__ __align__(256) int g_rowptr[Nn + 1];
__device__ __align__(256) int g_cursor[Nn];
__device__ __align__(256) int g_srcs[Ee];

// ---- packed f32x2 helpers (sm_103a FFMA2) ----
__device__ __forceinline__ unsigned long long pk2(float lo, float hi) {
    unsigned long long r;
    asm("mov.b64 %0, {%1, %2};" : "=l"(r) : "f"(lo), "f"(hi));
    return r;
}
__device__ __forceinline__ void fma2(unsigned long long& d,
                                     unsigned long long a, unsigned long long b) {
    asm("fma.rn.f32x2 %0, %1, %2, %0;" : "+l"(d) : "l"(a), "l"(b));
}
__device__ __forceinline__ void unpk2(float& lo, float& hi, unsigned long long v) {
    asm("mov.b64 {%0, %1}, %2;" : "=f"(lo), "=f"(hi) : "l"(v));
}

// ---------------------------------------------------------------------------
__global__ void zero_deg_kernel(int* __restrict__ deg) {
    int i = blockIdx.x * blockDim.x + threadIdx.x;
    if (i < Nn) deg[i] = 0;
}

__global__ void count_kernel(const int* __restrict__ ei, int* __restrict__ deg) {
    int e = blockIdx.x * blockDim.x + threadIdx.x;
    if (e < Ee) atomicAdd(&deg[ei[Ee + e]], 1);
}

// single-block exclusive scan over deg -> rowptr, cursor
__global__ void scan_kernel(const int* __restrict__ deg,
                            int* __restrict__ rowptr, int* __restrict__ cursor) {
    __shared__ int wsum[32];
    __shared__ int s_carry;
    int t = threadIdx.x;              // 1024 threads
    int lane = t & 31, wid = t >> 5;
    if (t == 0) s_carry = 0;
    __syncthreads();
    for (int base = 0; base < Nn; base += 1024) {
        int idx = base + t;
        int v = (idx < Nn) ? deg[idx] : 0;
        int inc = v;
        #pragma unroll
        for (int d = 1; d < 32; d <<= 1) {
            int o = __shfl_up_sync(0xffffffffu, inc, d);
            if (lane >= d) inc += o;
        }
        if (lane == 31) wsum[wid] = inc;
        __syncthreads();
        if (wid == 0) {
            int wv = wsum[lane];
            int winc = wv;
            #pragma unroll
            for (int d = 1; d < 32; d <<= 1) {
                int o = __shfl_up_sync(0xffffffffu, winc, d);
                if (lane >= d) winc += o;
            }
            wsum[lane] = winc - wv;
        }
        __syncthreads();
        int excl = s_carry + wsum[wid] + inc - v;
        if (idx < Nn) { rowptr[idx] = excl; cursor[idx] = excl; }
        __syncthreads();
        if (t == 1023) s_carry += wsum[31] + inc;
        __syncthreads();
    }
    if (t == 0) rowptr[Nn] = s_carry;
}

__global__ void fill_kernel(const int* __restrict__ ei,
                            int* __restrict__ cursor, int* __restrict__ srcs) {
    int e = blockIdx.x * blockDim.x + threadIdx.x;
    if (e >= Ee) return;
    int s = ei[e];
    int d = ei[Ee + e];
    int slot = atomicAdd(&cursor[d], 1);
    srcs[slot] = s;
}

// ---------------------------------------------------------------------------
// one warp per node: agg[node] = x[node] + sum_{s in in(node)} x[s]
// two independent accumulators + deep unroll for load ILP
__global__ void gather_kernel(const float* __restrict__ x,
                              const int* __restrict__ rowptr,
                              const int* __restrict__ srcs,
                              float* __restrict__ agg) {
    int gid  = blockIdx.x * blockDim.x + threadIdx.x;
    int node = gid >> 5;
    int lane = gid & 31;
    if (node >= Nn) return;
    int beg = rowptr[node], end = rowptr[node + 1];
    const float* xb = x + lane * 4;
    float4 a0 = __ldg((const float4*)(xb + (size_t)node * Ff));
    float4 a1 = make_float4(0.f, 0.f, 0.f, 0.f);
    for (int e0 = beg; e0 < end; e0 += 32) {
        int my = (e0 + lane < end) ? srcs[e0 + lane] : -1;
        int cnt = min(end - e0, 32);
        int j = 0;
        #pragma unroll 4
        for (; j + 2 <= cnt; j += 2) {
            int s0 = __shfl_sync(0xffffffffu, my, j);
            int s1 = __shfl_sync(0xffffffffu, my, j + 1);
            float4 v0 = __ldg((const float4*)(xb + (size_t)s0 * Ff));
            float4 v1 = __ldg((const float4*)(xb + (size_t)s1 * Ff));
            a0.x += v0.x; a0.y += v0.y; a0.z += v0.z; a0.w += v0.w;
            a1.x += v1.x; a1.y += v1.y; a1.z += v1.z; a1.w += v1.w;
        }
        if (j < cnt) {
            int s0 = __shfl_sync(0xffffffffu, my, j);
            float4 v0 = __ldg((const float4*)(xb + (size_t)s0 * Ff));
            a0.x += v0.x; a0.y += v0.y; a0.z += v0.z; a0.w += v0.w;
        }
    }
    a0.x += a1.x; a0.y += a1.y; a0.z += a1.z; a0.w += a1.w;
    *(float4*)(agg + (size_t)node * Ff + lane * 4) = a0;
}

// ---------------------------------------------------------------------------
// fused MLP with packed f32x2 FMA: xout = relu(BN(relu(agg@W1+b1)@W2+b2))
// 512 threads, 64-node tile; sH reused as intermediate M buffer.
__global__ void mlp_kernel(const float* __restrict__ agg,
                           const float* __restrict__ W1, const float* __restrict__ b1,
                           const float* __restrict__ W2, const float* __restrict__ b2,
                           const float* __restrict__ gamma, const float* __restrict__ beta,
                           const float* __restrict__ rmean, const float* __restrict__ rvar,
                           float* __restrict__ xout) {
    extern __shared__ float sm[];
    float* sW1 = sm;                       // 128*128
    float* sW2 = sm + 128 * 128;           // 128*128
    float* sH  = sm + 2 * 128 * 128;       // 64*128 (input, then M)

    int t = threadIdx.x;
    int row0 = blockIdx.x * TILE_M;

    #pragma unroll
    for (int i = t; i < (128 * 128) / 4; i += MLP_THREADS) {
        ((float4*)sW1)[i] = ((const float4*)W1)[i];
        ((float4*)sW2)[i] = ((const float4*)W2)[i];
    }
    for (int i = t; i < (TILE_M * 128) / 4; i += MLP_THREADS) {
        int r = i >> 5;     // 32 float4 per row
        if (row0 + r < Nn)
            ((float4*)sH)[i] = ((const float4*)agg)[(size_t)row0 * 32 + i];
        else
            ((float4*)sH)[i] = make_float4(0.f, 0.f, 0.f, 0.f);
    }
    __syncthreads();

    int tx = t & 31;   // cols tx*4 .. tx*4+3
    int ty = t >> 5;   // rows ty*4 .. ty*4+3  (ty in 0..15)

    unsigned long long acc[4][2];   // [row][col-pair]
    #pragma unroll
    for (int r = 0; r < 4; r++) { acc[r][0] = 0ull; acc[r][1] = 0ull; }

    // ---- GEMM1 ----
    #pragma unroll 4
    for (int kc = 0; kc < 32; kc++) {
        float4 h[4];
        #pragma unroll
        for (int r = 0; r < 4; r++)
            h[r] = ((const float4*)(sH + (ty * 4 + r) * 128))[kc];
        #pragma unroll
        for (int kk = 0; kk < 4; kk++) {
            ulonglong2 w = ((const ulonglong2*)(sW1 + (kc * 4 + kk) * 128))[tx];
            #pragma unroll
            for (int r = 0; r < 4; r++) {
                float hv = ((const float*)&h[r])[kk];
                unsigned long long hh = pk2(hv, hv);
                fma2(acc[r][0], hh, w.x);
                fma2(acc[r][1], hh, w.y);
            }
        }
    }
    __syncthreads();   // all reads of sH done before overwrite
    {
        float4 bb = ((const float4*)b1)[tx];
        #pragma unroll
        for (int r = 0; r < 4; r++) {
            float4 v;
            unpk2(v.x, v.y, acc[r][0]);
            unpk2(v.z, v.w, acc[r][1]);
            v.x = fmaxf(v.x + bb.x, 0.f);
            v.y = fmaxf(v.y + bb.y, 0.f);
            v.z = fmaxf(v.z + bb.z, 0.f);
            v.w = fmaxf(v.w + bb.w, 0.f);
            ((float4*)(sH + (ty * 4 + r) * 128))[tx] = v;
        }
    }
    __syncthreads();

    // ---- GEMM2 + BN + ReLU ----
    #pragma unroll
    for (int r = 0; r < 4; r++) { acc[r][0] = 0ull; acc[r][1] = 0ull; }

    #pragma unroll 4
    for (int kc = 0; kc < 32; kc++) {
        float4 h[4];
        #pragma unroll
        for (int r = 0; r < 4; r++)
            h[r] = ((const float4*)(sH + (ty * 4 + r) * 128))[kc];
        #pragma unroll
        for (int kk = 0; kk < 4; kk++) {
            ulonglong2 w = ((const ulonglong2*)(sW2 + (kc * 4 + kk) * 128))[tx];
            #pragma unroll
            for (int r = 0; r < 4; r++) {
                float hv = ((const float*)&h[r])[kk];
                unsigned long long hh = pk2(hv, hv);
                fma2(acc[r][0], hh, w.x);
                fma2(acc[r][1], hh, w.y);
            }
        }
    }
    {
        float4 bb = ((const float4*)b2)[tx];
        float4 gm = ((const float4*)gamma)[tx];
        float4 bt = ((const float4*)beta)[tx];
        float4 rm = ((const float4*)rmean)[tx];
        float4 rv = ((const float4*)rvar)[tx];
        float4 is;
        is.x = rsqrtf(rv.x + BN_EPS); is.y = rsqrtf(rv.y + BN_EPS);
        is.z = rsqrtf(rv.z + BN_EPS); is.w = rsqrtf(rv.w + BN_EPS);
        #pragma unroll
        for (int r = 0; r < 4; r++) {
            int row = row0 + ty * 4 + r;
            if (row < Nn) {
                float4 a;
                unpk2(a.x, a.y, acc[r][0]);
                unpk2(a.z, a.w, acc[r][1]);
                float4 v;
                v.x = fmaxf((a.x + bb.x - rm.x) * is.x * gm.x + bt.x, 0.f);
                v.y = fmaxf((a.y + bb.y - rm.y) * is.y * gm.y + bt.y, 0.f);
                v.z = fmaxf((a.z + bb.z - rm.z) * is.z * gm.z + bt.z, 0.f);
                v.w = fmaxf((a.w + bb.w - rm.w) * is.w * gm.w + bt.w, 0.f);
                ((float4*)(xout + (size_t)row * 128))[tx] = v;
            }
        }
    }
}

// ---------------------------------------------------------------------------
__global__ void zero_pool_kernel(float* __restrict__ pool, float* __restrict__ cnt) {
    int i = blockIdx.x * blockDim.x + threadIdx.x;
    if (i < Gg * Ff) pool[i] = 0.f;
    if (i < Gg) cnt[i] = 0.f;
}

__global__ void pool_kernel(const float* __restrict__ x,
                            const int* __restrict__ batch,
                            float* __restrict__ pool, float* __restrict__ cnt) {
    int gid  = blockIdx.x * blockDim.x + threadIdx.x;
    int node = gid >> 5;
    int lane = gid & 31;
    if (node >= Nn) return;
    int g = batch[node];
    float4 v = *(const float4*)(x + (size_t)node * Ff + lane * 4);
    float* p = pool + g * Ff + lane * 4;
    asm volatile("red.global.add.v4.f32 [%0], {%1,%2,%3,%4};"
                 :: "l"(p), "f"(v.x), "f"(v.y), "f"(v.z), "f"(v.w) : "memory");
    if (lane == 0) atomicAdd(&cnt[g], 1.0f);
}

// ---------------------------------------------------------------------------
__global__ void final_kernel(const float* __restrict__ pool, const float* __restrict__ cnt,
                             const float* __restrict__ fc_w, const float* __restrict__ fc_b,
                             float* __restrict__ out) {
    int g = threadIdx.x;
    if (g >= Gg) return;
    float inv = 1.0f / fmaxf(cnt[g], 1.0f);
    float logits[Cc];
    #pragma unroll
    for (int j = 0; j < Cc; j++) logits[j] = fc_b[j];
    for (int k = 0; k < Ff; k++) {
        float p = pool[g * Ff + k] * inv;
        #pragma unroll
        for (int j = 0; j < Cc; j++) logits[j] += p * fc_w[k * Cc + j];
    }
    float m = logits[0];
    #pragma unroll
    for (int j = 1; j < Cc; j++) m = fmaxf(m, logits[j]);
    float s = 0.f;
    #pragma unroll
    for (int j = 0; j < Cc; j++) s += expf(logits[j] - m);
    float ls = logf(s) + m;
    #pragma unroll
    for (int j = 0; j < Cc; j++) out[g * Cc + j] = logits[j] - ls;
}

// ---------------------------------------------------------------------------
extern "C" void kernel_launch(void* const* d_in, const int* in_sizes, int n_in,
                              void* d_out, int out_size) {
    const float* x     = (const float*)d_in[0];
    const int*   ei    = (const int*)d_in[1];
    const int*   batch = (const int*)d_in[2];
    const float* W1    = (const float*)d_in[3];
    const float* b1    = (const float*)d_in[4];
    const float* W2    = (const float*)d_in[5];
    const float* b2    = (const float*)d_in[6];
    const float* gamma = (const float*)d_in[7];
    const float* beta  = (const float*)d_in[8];
    const float* rmean = (const float*)d_in[9];
    const float* rvar  = (const float*)d_in[10];
    const float* fc_w  = (const float*)d_in[11];
    const float* fc_b  = (const float*)d_in[12];
    float* out = (float*)d_out;

    cudaFuncSetAttribute(mlp_kernel, cudaFuncAttributeMaxDynamicSharedMemorySize, MLP_SMEM);

    float *agg, *x1, *x2, *pool, *cnt;
    int *deg, *rowptr, *cursor, *srcs;
    cudaGetSymbolAddress((void**)&agg,    g_agg);
    cudaGetSymbolAddress((void**)&x1,     g_x1);
    cudaGetSymbolAddress((void**)&x2,     g_x2);
    cudaGetSymbolAddress((void**)&pool,   g_pool);
    cudaGetSymbolAddress((void**)&cnt,    g_cnt);
    cudaGetSymbolAddress((void**)&deg,    g_deg);
    cudaGetSymbolAddress((void**)&rowptr, g_rowptr);
    cudaGetSymbolAddress((void**)&cursor, g_cursor);
    cudaGetSymbolAddress((void**)&srcs,   g_srcs);

    const int mlp_blocks    = (Nn + TILE_M - 1) / TILE_M;
    const int gather_blocks = (Nn * 32 + 255) / 256;
    const int pool_blocks   = (Nn * 32 + 255) / 256;

    // build CSR (dst-sorted) once per launch
    zero_deg_kernel<<<(Nn + 255) / 256, 256>>>(deg);
    count_kernel<<<(Ee + 255) / 256, 256>>>(ei, deg);
    scan_kernel<<<1, 1024>>>(deg, rowptr, cursor);
    fill_kernel<<<(Ee + 255) / 256, 256>>>(ei, cursor, srcs);

    const float* cur = x;
    float* outs[Ll] = { x1, x2, x1 };
    for (int l = 0; l < Ll; l++) {
        gather_kernel<<<gather_blocks, 256>>>(cur, rowptr, srcs, agg);
        mlp_kernel<<<mlp_blocks, MLP_THREADS, MLP_SMEM>>>(
            agg,
            W1 + (size_t)l * 128 * 128, b1 + (size_t)l * 128,
            W2 + (size_t)l * 128 * 128, b2 + (size_t)l * 128,
            gamma + (size_t)l * 128, beta + (size_t)l * 128,
            rmean + (size_t)l * 128, rvar + (size_t)l * 128,
            outs[l]);
        cur = outs[l];
    }

    zero_pool_kernel<<<(Gg * Ff + 255) / 256, 256>>>(pool, cnt);
    pool_kernel<<<pool_blocks, 256>>>(cur, batch, pool, cnt);
    final_kernel<<<1, 128>>>(pool, cnt, fc_w, fc_b, out);
}

// round 9
// speedup vs baseline: 1.6787x; 1.0364x over previous
#include <cuda_runtime.h>
#include <math.h>

#define Nn 50000
#define Ee 1600000
#define Ff 128
#define Ll 3
#define Gg 128
#define Cc 10
#define BN_EPS 1e-5f

#define TILE_M 64
#define MLP_THREADS 512
#define MLP_GRID 148
#define NTILES ((Nn + TILE_M - 1) / TILE_M)          // 782
#define MLP_SMEM ((2*128*128 + 2*TILE_M*128) * 4)    // 196608 B

// scratch (device globals — no allocation allowed)
__device__ __align__(256) float g_agg[(size_t)Nn * Ff];
__device__ __align__(256) float g_x1[(size_t)Nn * Ff];
__device__ __align__(256) float g_x2[(size_t)Nn * Ff];
__device__ __align__(256) float g_pool[Gg * Ff];
__device__ __align__(256) float g_cnt[Gg];
// CSR scratch
__device__ __align__(256) int g_deg[Nn];
__device__ __align__(256) int g_rowptr[Nn + 1];
__device__ __align__(256) int g_cursor[Nn];
__device__ __align__(256) int g_srcs[Ee];

// ---- packed f32x2 helpers (sm_103a FFMA2) ----
__device__ __forceinline__ unsigned long long pk2(float lo, float hi) {
    unsigned long long r;
    asm("mov.b64 %0, {%1, %2};" : "=l"(r) : "f"(lo), "f"(hi));
    return r;
}
__device__ __forceinline__ void fma2(unsigned long long& d,
                                     unsigned long long a, unsigned long long b) {
    asm("fma.rn.f32x2 %0, %1, %2, %0;" : "+l"(d) : "l"(a), "l"(b));
}
__device__ __forceinline__ void unpk2(float& lo, float& hi, unsigned long long v) {
    asm("mov.b64 {%0, %1}, %2;" : "=f"(lo), "=f"(hi) : "l"(v));
}

// ---- cp.async helpers ----
__device__ __forceinline__ unsigned smem_u32(const void* p) {
    return (unsigned)__cvta_generic_to_shared(p);
}
__device__ __forceinline__ void cpa16(unsigned dst, const void* src, bool pred) {
    int sz = pred ? 16 : 0;
    asm volatile("cp.async.cg.shared.global [%0], [%1], 16, %2;"
                 :: "r"(dst), "l"(src), "r"(sz) : "memory");
}
__device__ __forceinline__ void cpa_commit() {
    asm volatile("cp.async.commit_group;" ::: "memory");
}

// ---------------------------------------------------------------------------
__global__ void zero_deg_kernel(int* __restrict__ deg) {
    int i = blockIdx.x * blockDim.x + threadIdx.x;
    if (i < Nn) deg[i] = 0;
}

__global__ void count_kernel(const int* __restrict__ ei, int* __restrict__ deg) {
    int e = blockIdx.x * blockDim.x + threadIdx.x;
    if (e < Ee) atomicAdd(&deg[ei[Ee + e]], 1);
}

// single-block exclusive scan over deg -> rowptr, cursor
__global__ void scan_kernel(const int* __restrict__ deg,
                            int* __restrict__ rowptr, int* __restrict__ cursor) {
    __shared__ int wsum[32];
    __shared__ int s_carry;
    int t = threadIdx.x;              // 1024 threads
    int lane = t & 31, wid = t >> 5;
    if (t == 0) s_carry = 0;
    __syncthreads();
    for (int base = 0; base < Nn; base += 1024) {
        int idx = base + t;
        int v = (idx < Nn) ? deg[idx] : 0;
        int inc = v;
        #pragma unroll
        for (int d = 1; d < 32; d <<= 1) {
            int o = __shfl_up_sync(0xffffffffu, inc, d);
            if (lane >= d) inc += o;
        }
        if (lane == 31) wsum[wid] = inc;
        __syncthreads();
        if (wid == 0) {
            int wv = wsum[lane];
            int winc = wv;
            #pragma unroll
            for (int d = 1; d < 32; d <<= 1) {
                int o = __shfl_up_sync(0xffffffffu, winc, d);
                if (lane >= d) winc += o;
            }
            wsum[lane] = winc - wv;
        }
        __syncthreads();
        int excl = s_carry + wsum[wid] + inc - v;
        if (idx < Nn) { rowptr[idx] = excl; cursor[idx] = excl; }
        __syncthreads();
        if (t == 1023) s_carry += wsum[31] + inc;
        __syncthreads();
    }
    if (t == 0) rowptr[Nn] = s_carry;
}

__global__ void fill_kernel(const int* __restrict__ ei,
                            int* __restrict__ cursor, int* __restrict__ srcs) {
    int e = blockIdx.x * blockDim.x + threadIdx.x;
    if (e >= Ee) return;
    int s = ei[e];
    int d = ei[Ee + e];
    int slot = atomicAdd(&cursor[d], 1);
    srcs[slot] = s;
}

// ---------------------------------------------------------------------------
// one warp per node: agg[node] = x[node] + sum_{s in in(node)} x[s]
// 4 independent accumulator chains for load ILP
__global__ void gather_kernel(const float* __restrict__ x,
                              const int* __restrict__ rowptr,
                              const int* __restrict__ srcs,
                              float* __restrict__ agg) {
    int gid  = blockIdx.x * blockDim.x + threadIdx.x;
    int node = gid >> 5;
    int lane = gid & 31;
    if (node >= Nn) return;
    int beg = rowptr[node], end = rowptr[node + 1];
    const float* xb = x + lane * 4;
    float4 a0 = __ldg((const float4*)(xb + (size_t)node * Ff));
    float4 a1 = make_float4(0.f, 0.f, 0.f, 0.f);
    float4 a2 = make_float4(0.f, 0.f, 0.f, 0.f);
    float4 a3 = make_float4(0.f, 0.f, 0.f, 0.f);
    for (int e0 = beg; e0 < end; e0 += 32) {
        int my = (e0 + lane < end) ? srcs[e0 + lane] : -1;
        int cnt = min(end - e0, 32);
        int j = 0;
        #pragma unroll 2
        for (; j + 4 <= cnt; j += 4) {
            int s0 = __shfl_sync(0xffffffffu, my, j);
            int s1 = __shfl_sync(0xffffffffu, my, j + 1);
            int s2 = __shfl_sync(0xffffffffu, my, j + 2);
            int s3 = __shfl_sync(0xffffffffu, my, j + 3);
            float4 v0 = __ldg((const float4*)(xb + (size_t)s0 * Ff));
            float4 v1 = __ldg((const float4*)(xb + (size_t)s1 * Ff));
            float4 v2 = __ldg((const float4*)(xb + (size_t)s2 * Ff));
            float4 v3 = __ldg((const float4*)(xb + (size_t)s3 * Ff));
            a0.x += v0.x; a0.y += v0.y; a0.z += v0.z; a0.w += v0.w;
            a1.x += v1.x; a1.y += v1.y; a1.z += v1.z; a1.w += v1.w;
            a2.x += v2.x; a2.y += v2.y; a2.z += v2.z; a2.w += v2.w;
            a3.x += v3.x; a3.y += v3.y; a3.z += v3.z; a3.w += v3.w;
        }
        for (; j < cnt; j++) {
            int s0 = __shfl_sync(0xffffffffu, my, j);
            float4 v0 = __ldg((const float4*)(xb + (size_t)s0 * Ff));
            a0.x += v0.x; a0.y += v0.y; a0.z += v0.z; a0.w += v0.w;
        }
    }
    a0.x += a1.x + a2.x + a3.x;
    a0.y += a1.y + a2.y + a3.y;
    a0.z += a1.z + a2.z + a3.z;
    a0.w += a1.w + a2.w + a3.w;
    *(float4*)(agg + (size_t)node * Ff + lane * 4) = a0;
}

// ---------------------------------------------------------------------------
// Persistent fused MLP: weights staged ONCE, tiles double-buffered via cp.async.
// xout = relu(BN(relu(agg@W1+b1)@W2+b2))
__global__ __launch_bounds__(MLP_THREADS, 1)
void mlp_kernel(const float* __restrict__ agg,
                const float* __restrict__ W1, const float* __restrict__ b1,
                const float* __restrict__ W2, const float* __restrict__ b2,
                const float* __restrict__ gamma, const float* __restrict__ beta,
                const float* __restrict__ rmean, const float* __restrict__ rvar,
                float* __restrict__ xout) {
    extern __shared__ float sm[];
    float* sW1 = sm;                        // 16384 floats
    float* sW2 = sm + 16384;                // 16384 floats
    float* sT0 = sm + 32768;                // 8192 floats (tile buf 0)
    float* sT1 = sm + 32768 + 8192;         // 8192 floats (tile buf 1)

    int t = threadIdx.x;
    unsigned base = smem_u32(sm);

    // stage weights once (cp.async group 0)
    for (int i = t; i < 4096; i += MLP_THREADS) {
        cpa16(base + i * 16,          (const float4*)W1 + i, true);
        cpa16(base + 65536 + i * 16,  (const float4*)W2 + i, true);
    }
    cpa_commit();

    int tx = t & 31;   // cols tx*4 .. tx*4+3
    int ty = t >> 5;   // rows ty*4 .. ty*4+3  (ty in 0..15)

    // prefetch first tile into buf 0
    {
        int tile = blockIdx.x;
        int row0 = tile * TILE_M;
        const float4* src = (const float4*)agg + (size_t)row0 * 32;
        unsigned dst = base + 131072;
        for (int i = t; i < 2048; i += MLP_THREADS) {
            bool ok = (row0 + (i >> 5)) < Nn;
            cpa16(dst + i * 16, ok ? (src + i) : (const float4*)agg, ok);
        }
        cpa_commit();
    }

    int p = 0;
    for (int tile = blockIdx.x; tile < NTILES; tile += MLP_GRID, p ^= 1) {
        int nxt = tile + MLP_GRID;
        bool have_nxt = nxt < NTILES;
        if (have_nxt) {
            int row0n = nxt * TILE_M;
            const float4* src = (const float4*)agg + (size_t)row0n * 32;
            unsigned dst = base + 131072 + (p ^ 1) * 32768;
            for (int i = t; i < 2048; i += MLP_THREADS) {
                bool ok = (row0n + (i >> 5)) < Nn;
                cpa16(dst + i * 16, ok ? (src + i) : (const float4*)agg, ok);
            }
            cpa_commit();
            asm volatile("cp.async.wait_group 1;" ::: "memory");
        } else {
            asm volatile("cp.async.wait_group 0;" ::: "memory");
        }
        __syncthreads();

        float* sH = p ? sT1 : sT0;
        int row0 = tile * TILE_M;

        unsigned long long acc[4][2];
        #pragma unroll
        for (int r = 0; r < 4; r++) { acc[r][0] = 0ull; acc[r][1] = 0ull; }

        // ---- GEMM1 ----
        #pragma unroll 4
        for (int kc = 0; kc < 32; kc++) {
            float4 h[4];
            #pragma unroll
            for (int r = 0; r < 4; r++)
                h[r] = ((const float4*)(sH + (ty * 4 + r) * 128))[kc];
            #pragma unroll
            for (int kk = 0; kk < 4; kk++) {
                ulonglong2 w = ((const ulonglong2*)(sW1 + (kc * 4 + kk) * 128))[tx];
                #pragma unroll
                for (int r = 0; r < 4; r++) {
                    float hv = ((const float*)&h[r])[kk];
                    unsigned long long hh = pk2(hv, hv);
                    fma2(acc[r][0], hh, w.x);
                    fma2(acc[r][1], hh, w.y);
                }
            }
        }
        __syncthreads();   // all reads of sH done before in-place overwrite
        {
            float4 bb = ((const float4*)b1)[tx];
            #pragma unroll
            for (int r = 0; r < 4; r++) {
                float4 v;
                unpk2(v.x, v.y, acc[r][0]);
                unpk2(v.z, v.w, acc[r][1]);
                v.x = fmaxf(v.x + bb.x, 0.f);
                v.y = fmaxf(v.y + bb.y, 0.f);
                v.z = fmaxf(v.z + bb.z, 0.f);
                v.w = fmaxf(v.w + bb.w, 0.f);
                ((float4*)(sH + (ty * 4 + r) * 128))[tx] = v;
            }
        }
        __syncthreads();

        // ---- GEMM2 + BN + ReLU ----
        #pragma unroll
        for (int r = 0; r < 4; r++) { acc[r][0] = 0ull; acc[r][1] = 0ull; }

        #pragma unroll 4
        for (int kc = 0; kc < 32; kc++) {
            float4 h[4];
            #pragma unroll
            for (int r = 0; r < 4; r++)
                h[r] = ((const float4*)(sH + (ty * 4 + r) * 128))[kc];
            #pragma unroll
            for (int kk = 0; kk < 4; kk++) {
                ulonglong2 w = ((const ulonglong2*)(sW2 + (kc * 4 + kk) * 128))[tx];
                #pragma unroll
                for (int r = 0; r < 4; r++) {
                    float hv = ((const float*)&h[r])[kk];
                    unsigned long long hh = pk2(hv, hv);
                    fma2(acc[r][0], hh, w.x);
                    fma2(acc[r][1], hh, w.y);
                }
            }
        }
        {
            float4 bb = ((const float4*)b2)[tx];
            float4 gm = ((const float4*)gamma)[tx];
            float4 bt = ((const float4*)beta)[tx];
            float4 rm = ((const float4*)rmean)[tx];
            float4 rv = ((const float4*)rvar)[tx];
            float4 is;
            is.x = rsqrtf(rv.x + BN_EPS); is.y = rsqrtf(rv.y + BN_EPS);
            is.z = rsqrtf(rv.z + BN_EPS); is.w = rsqrtf(rv.w + BN_EPS);
            #pragma unroll
            for (int r = 0; r < 4; r++) {
                int row = row0 + ty * 4 + r;
                if (row < Nn) {
                    float4 a;
                    unpk2(a.x, a.y, acc[r][0]);
                    unpk2(a.z, a.w, acc[r][1]);
                    float4 v;
                    v.x = fmaxf((a.x + bb.x - rm.x) * is.x * gm.x + bt.x, 0.f);
                    v.y = fmaxf((a.y + bb.y - rm.y) * is.y * gm.y + bt.y, 0.f);
                    v.z = fmaxf((a.z + bb.z - rm.z) * is.z * gm.z + bt.z, 0.f);
                    v.w = fmaxf((a.w + bb.w - rm.w) * is.w * gm.w + bt.w, 0.f);
                    ((float4*)(xout + (size_t)row * 128))[tx] = v;
                }
            }
        }
        __syncthreads();   // buf p must be fully read before next prefetch reuses it
    }
}

// ---------------------------------------------------------------------------
__global__ void zero_pool_kernel(float* __restrict__ pool, float* __restrict__ cnt) {
    int i = blockIdx.x * blockDim.x + threadIdx.x;
    if (i < Gg * Ff) pool[i] = 0.f;
    if (i < Gg) cnt[i] = 0.f;
}

__global__ void pool_kernel(const float* __restrict__ x,
                            const int* __restrict__ batch,
                            float* __restrict__ pool, float* __restrict__ cnt) {
    int gid  = blockIdx.x * blockDim.x + threadIdx.x;
    int node = gid >> 5;
    int lane = gid & 31;
    if (node >= Nn) return;
    int g = batch[node];
    float4 v = *(const float4*)(x + (size_t)node * Ff + lane * 4);
    float* p = pool + g * Ff + lane * 4;
    asm volatile("red.global.add.v4.f32 [%0], {%1,%2,%3,%4};"
                 :: "l"(p), "f"(v.x), "f"(v.y), "f"(v.z), "f"(v.w) : "memory");
    if (lane == 0) atomicAdd(&cnt[g], 1.0f);
}

// ---------------------------------------------------------------------------
__global__ void final_kernel(const float* __restrict__ pool, const float* __restrict__ cnt,
                             const float* __restrict__ fc_w, const float* __restrict__ fc_b,
                             float* __restrict__ out) {
    int g = threadIdx.x;
    if (g >= Gg) return;
    float inv = 1.0f / fmaxf(cnt[g], 1.0f);
    float logits[Cc];
    #pragma unroll
    for (int j = 0; j < Cc; j++) logits[j] = fc_b[j];
    for (int k = 0; k < Ff; k++) {
        float p = pool[g * Ff + k] * inv;
        #pragma unroll
        for (int j = 0; j < Cc; j++) logits[j] += p * fc_w[k * Cc + j];
    }
    float m = logits[0];
    #pragma unroll
    for (int j = 1; j < Cc; j++) m = fmaxf(m, logits[j]);
    float s = 0.f;
    #pragma unroll
    for (int j = 0; j < Cc; j++) s += expf(logits[j] - m);
    float ls = logf(s) + m;
    #pragma unroll
    for (int j = 0; j < Cc; j++) out[g * Cc + j] = logits[j] - ls;
}

// ---------------------------------------------------------------------------
extern "C" void kernel_launch(void* const* d_in, const int* in_sizes, int n_in,
                              void* d_out, int out_size) {
    const float* x     = (const float*)d_in[0];
    const int*   ei    = (const int*)d_in[1];
    const int*   batch = (const int*)d_in[2];
    const float* W1    = (const float*)d_in[3];
    const float* b1    = (const float*)d_in[4];
    const float* W2    = (const float*)d_in[5];
    const float* b2    = (const float*)d_in[6];
    const float* gamma = (const float*)d_in[7];
    const float* beta  = (const float*)d_in[8];
    const float* rmean = (const float*)d_in[9];
    const float* rvar  = (const float*)d_in[10];
    const float* fc_w  = (const float*)d_in[11];
    const float* fc_b  = (const float*)d_in[12];
    float* out = (float*)d_out;

    cudaFuncSetAttribute(mlp_kernel, cudaFuncAttributeMaxDynamicSharedMemorySize, MLP_SMEM);

    float *agg, *x1, *x2, *pool, *cnt;
    int *deg, *rowptr, *cursor, *srcs;
    cudaGetSymbolAddress((void**)&agg,    g_agg);
    cudaGetSymbolAddress((void**)&x1,     g_x1);
    cudaGetSymbolAddress((void**)&x2,     g_x2);
    cudaGetSymbolAddress((void**)&pool,   g_pool);
    cudaGetSymbolAddress((void**)&cnt,    g_cnt);
    cudaGetSymbolAddress((void**)&deg,    g_deg);
    cudaGetSymbolAddress((void**)&rowptr, g_rowptr);
    cudaGetSymbolAddress((void**)&cursor, g_cursor);
    cudaGetSymbolAddress((void**)&srcs,   g_srcs);

    const int gather_blocks = (Nn * 32 + 255) / 256;
    const int pool_blocks   = (Nn * 32 + 255) / 256;

    // build CSR (dst-sorted) once per launch
    zero_deg_kernel<<<(Nn + 255) / 256, 256>>>(deg);
    count_kernel<<<(Ee + 255) / 256, 256>>>(ei, deg);
    scan_kernel<<<1, 1024>>>(deg, rowptr, cursor);
    fill_kernel<<<(Ee + 255) / 256, 256>>>(ei, cursor, srcs);

    const float* cur = x;
    float* outs[Ll] = { x1, x2, x1 };
    for (int l = 0; l < Ll; l++) {
        gather_kernel<<<gather_blocks, 256>>>(cur, rowptr, srcs, agg);
        mlp_kernel<<<MLP_GRID, MLP_THREADS, MLP_SMEM>>>(
            agg,
            W1 + (size_t)l * 128 * 128, b1 + (size_t)l * 128,
            W2 + (size_t)l * 128 * 128, b2 + (size_t)l * 128,
            gamma + (size_t)l * 128, beta + (size_t)l * 128,
            rmean + (size_t)l * 128, rvar + (size_t)l * 128,
            outs[l]);
        cur = outs[l];
    }

    zero_pool_kernel<<<(Gg * Ff + 255) / 256, 256>>>(pool, cnt);
    pool_kernel<<<pool_blocks, 256>>>(cur, batch, pool, cnt);
    final_kernel<<<1, 128>>>(pool, cnt, fc_w, fc_b, out);
}

// round 10
// speedup vs baseline: 2.3245x; 1.3847x over previous
#include <cuda_runtime.h>
#include <math.h>

#define Nn 50000
#define Ee 1600000
#define Ff 128
#define Ll 3
#define Gg 128
#define Cc 10
#define BN_EPS 1e-5f

#define TILE_M 64
#define MLP_THREADS 512
#define MLP_GRID 148
#define NTILES ((Nn + TILE_M - 1) / TILE_M)          // 782
#define MLP_SMEM ((2*128*128 + 2*TILE_M*128) * 4)    // 196608 B

// scratch (device globals — no allocation allowed)
__device__ __align__(256) float g_agg[(size_t)Nn * Ff];
__device__ __align__(256) float g_x1[(size_t)Nn * Ff];
__device__ __align__(256) float g_x2[(size_t)Nn * Ff];
__device__ __align__(256) float g_pool[Gg * Ff];
__device__ __align__(256) float g_cnt[Gg];
// CSR scratch
__device__ __align__(256) int g_deg[Nn];
__device__ __align__(256) int g_rowptr[Nn + 1];
__device__ __align__(256) int g_cursor[Nn];
__device__ __align__(256) int g_srcs[Ee];

// ---- tf32 helpers ----
__device__ __forceinline__ unsigned f2tf32(float f) {
    unsigned r;
    asm("cvt.rna.tf32.f32 %0, %1;" : "=r"(r) : "f"(f));
    return r;
}
__device__ __forceinline__ void mma_tf32(float& d0, float& d1, float& d2, float& d3,
                                         unsigned a0, unsigned a1, unsigned a2, unsigned a3,
                                         unsigned b0, unsigned b1) {
    asm("mma.sync.aligned.m16n8k8.row.col.f32.tf32.tf32.f32 "
        "{%0,%1,%2,%3},{%4,%5,%6,%7},{%8,%9},{%0,%1,%2,%3};"
        : "+f"(d0), "+f"(d1), "+f"(d2), "+f"(d3)
        : "r"(a0), "r"(a1), "r"(a2), "r"(a3), "r"(b0), "r"(b1));
}

// ---- cp.async helpers ----
__device__ __forceinline__ unsigned smem_u32(const void* p) {
    return (unsigned)__cvta_generic_to_shared(p);
}
__device__ __forceinline__ void cpa16(unsigned dst, const void* src, bool pred) {
    int sz = pred ? 16 : 0;
    asm volatile("cp.async.cg.shared.global [%0], [%1], 16, %2;"
                 :: "r"(dst), "l"(src), "r"(sz) : "memory");
}
__device__ __forceinline__ void cpa_commit() {
    asm volatile("cp.async.commit_group;" ::: "memory");
}

// ---------------------------------------------------------------------------
__global__ void zero_deg_kernel(int* __restrict__ deg) {
    int i = blockIdx.x * blockDim.x + threadIdx.x;
    if (i < Nn) deg[i] = 0;
}

__global__ void count_kernel(const int* __restrict__ ei, int* __restrict__ deg) {
    int e = blockIdx.x * blockDim.x + threadIdx.x;
    if (e < Ee) atomicAdd(&deg[ei[Ee + e]], 1);
}

// single-block exclusive scan over deg -> rowptr, cursor
__global__ void scan_kernel(const int* __restrict__ deg,
                            int* __restrict__ rowptr, int* __restrict__ cursor) {
    __shared__ int wsum[32];
    __shared__ int s_carry;
    int t = threadIdx.x;              // 1024 threads
    int lane = t & 31, wid = t >> 5;
    if (t == 0) s_carry = 0;
    __syncthreads();
    for (int base = 0; base < Nn; base += 1024) {
        int idx = base + t;
        int v = (idx < Nn) ? deg[idx] : 0;
        int inc = v;
        #pragma unroll
        for (int d = 1; d < 32; d <<= 1) {
            int o = __shfl_up_sync(0xffffffffu, inc, d);
            if (lane >= d) inc += o;
        }
        if (lane == 31) wsum[wid] = inc;
        __syncthreads();
        if (wid == 0) {
            int wv = wsum[lane];
            int winc = wv;
            #pragma unroll
            for (int d = 1; d < 32; d <<= 1) {
                int o = __shfl_up_sync(0xffffffffu, winc, d);
                if (lane >= d) winc += o;
            }
            wsum[lane] = winc - wv;
        }
        __syncthreads();
        int excl = s_carry + wsum[wid] + inc - v;
        if (idx < Nn) { rowptr[idx] = excl; cursor[idx] = excl; }
        __syncthreads();
        if (t == 1023) s_carry += wsum[31] + inc;
        __syncthreads();
    }
    if (t == 0) rowptr[Nn] = s_carry;
}

__global__ void fill_kernel(const int* __restrict__ ei,
                            int* __restrict__ cursor, int* __restrict__ srcs) {
    int e = blockIdx.x * blockDim.x + threadIdx.x;
    if (e >= Ee) return;
    int s = ei[e];
    int d = ei[Ee + e];
    int slot = atomicAdd(&cursor[d], 1);
    srcs[slot] = s;
}

// ---------------------------------------------------------------------------
// one warp per node: agg[node] = x[node] + sum_{s in in(node)} x[s]
// result rounded to tf32 (rna) — agg only feeds the tensor-core MLP.
__global__ void gather_kernel(const float* __restrict__ x,
                              const int* __restrict__ rowptr,
                              const int* __restrict__ srcs,
                              float* __restrict__ agg) {
    int gid  = blockIdx.x * blockDim.x + threadIdx.x;
    int node = gid >> 5;
    int lane = gid & 31;
    if (node >= Nn) return;
    int beg = rowptr[node], end = rowptr[node + 1];
    const float* xb = x + lane * 4;
    float4 a0 = __ldg((const float4*)(xb + (size_t)node * Ff));
    float4 a1 = make_float4(0.f, 0.f, 0.f, 0.f);
    float4 a2 = make_float4(0.f, 0.f, 0.f, 0.f);
    float4 a3 = make_float4(0.f, 0.f, 0.f, 0.f);
    for (int e0 = beg; e0 < end; e0 += 32) {
        int my = (e0 + lane < end) ? srcs[e0 + lane] : -1;
        int cnt = min(end - e0, 32);
        int j = 0;
        #pragma unroll 2
        for (; j + 4 <= cnt; j += 4) {
            int s0 = __shfl_sync(0xffffffffu, my, j);
            int s1 = __shfl_sync(0xffffffffu, my, j + 1);
            int s2 = __shfl_sync(0xffffffffu, my, j + 2);
            int s3 = __shfl_sync(0xffffffffu, my, j + 3);
            float4 v0 = __ldg((const float4*)(xb + (size_t)s0 * Ff));
            float4 v1 = __ldg((const float4*)(xb + (size_t)s1 * Ff));
            float4 v2 = __ldg((const float4*)(xb + (size_t)s2 * Ff));
            float4 v3 = __ldg((const float4*)(xb + (size_t)s3 * Ff));
            a0.x += v0.x; a0.y += v0.y; a0.z += v0.z; a0.w += v0.w;
            a1.x += v1.x; a1.y += v1.y; a1.z += v1.z; a1.w += v1.w;
            a2.x += v2.x; a2.y += v2.y; a2.z += v2.z; a2.w += v2.w;
            a3.x += v3.x; a3.y += v3.y; a3.z += v3.z; a3.w += v3.w;
        }
        for (; j < cnt; j++) {
            int s0 = __shfl_sync(0xffffffffu, my, j);
            float4 v0 = __ldg((const float4*)(xb + (size_t)s0 * Ff));
            a0.x += v0.x; a0.y += v0.y; a0.z += v0.z; a0.w += v0.w;
        }
    }
    a0.x += a1.x + a2.x + a3.x;
    a0.y += a1.y + a2.y + a3.y;
    a0.z += a1.z + a2.z + a3.z;
    a0.w += a1.w + a2.w + a3.w;
    // round to tf32 (to-nearest) so the MMA consumes unbiased operands
    a0.x = __uint_as_float(f2tf32(a0.x));
    a0.y = __uint_as_float(f2tf32(a0.y));
    a0.z = __uint_as_float(f2tf32(a0.z));
    a0.w = __uint_as_float(f2tf32(a0.w));
    *(float4*)(agg + (size_t)node * Ff + lane * 4) = a0;
}

// ---------------------------------------------------------------------------
// Persistent tensor-core MLP (tf32 mma.sync.m16n8k8).
// Weights staged once + rounded to tf32 in SMEM; tiles double-buffered cp.async.
// SMEM layouts XOR-swizzled for conflict-free fragment loads:
//   A (tile/M):  float col c stored at c ^ ((row&7)<<2)   (16B-chunk XOR)
//   B (weights): float col n stored at n ^ ((k&3)<<3)     (16B-chunk XOR)
__global__ __launch_bounds__(MLP_THREADS, 1)
void mlp_kernel(const float* __restrict__ agg,
                const float* __restrict__ W1, const float* __restrict__ b1g,
                const float* __restrict__ W2, const float* __restrict__ b2g,
                const float* __restrict__ gamma, const float* __restrict__ beta,
                const float* __restrict__ rmean, const float* __restrict__ rvar,
                float* __restrict__ xout) {
    extern __shared__ float sm[];
    float* sW1 = sm;                        // 16384 floats
    float* sW2 = sm + 16384;                // 16384 floats
    float* sT0 = sm + 32768;                // 8192 floats (tile buf 0)
    float* sT1 = sm + 32768 + 8192;         // 8192 floats (tile buf 1)

    int t = threadIdx.x;
    int lane = t & 31;
    int warp = t >> 5;
    int wm = warp & 3;        // m-group: rows wm*16 .. +16
    int wn = warp >> 2;       // n-group: cols wn*32 .. +32
    unsigned base = smem_u32(sm);

    // ---- stage weights once, swizzled (group W) ----
    for (int i = t; i < 4096; i += MLP_THREADS) {
        int k = i >> 5, n4 = i & 31;
        int dchunk = (i & ~31) | (n4 ^ ((k & 3) << 1));
        cpa16(base + dchunk * 16,         (const float4*)W1 + i, true);
        cpa16(base + 65536 + dchunk * 16, (const float4*)W2 + i, true);
    }
    cpa_commit();

    // ---- prefetch first tile into buf 0, swizzled ----
    {
        int row0 = blockIdx.x * TILE_M;
        const float4* src = (const float4*)agg + (size_t)row0 * 32;
        unsigned dst = base + 131072;
        for (int i = t; i < 2048; i += MLP_THREADS) {
            int row = i >> 5, c4 = i & 31;
            int dchunk = (i & ~31) | (c4 ^ (row & 7));
            bool ok = (row0 + row) < Nn;
            cpa16(dst + dchunk * 16, ok ? (src + i) : (const float4*)agg, ok);
        }
        cpa_commit();
    }

    // wait for weights, round them to tf32 in place
    asm volatile("cp.async.wait_group 1;" ::: "memory");
    __syncthreads();
    for (int i = t; i < 8192; i += MLP_THREADS) {
        float4 v = ((float4*)sm)[i];
        v.x = __uint_as_float(f2tf32(v.x));
        v.y = __uint_as_float(f2tf32(v.y));
        v.z = __uint_as_float(f2tf32(v.z));
        v.w = __uint_as_float(f2tf32(v.w));
        ((float4*)sm)[i] = v;
    }
    __syncthreads();

    // ---- per-thread fragment geometry ----
    int ar  = wm * 16 + (lane >> 2);          // A rows: ar, ar+8
    int acl = lane & 3;                       // A col low bits
    int s1  = (lane >> 2) << 2;               // A swizzle key ((ar&7)<<2)
    int arO  = ar * 128;
    int arO8 = arO + 1024;
    int kl = lane & 3;                        // B k low bits
    int cidx[4];                              // B swizzled col index per n8 block
    #pragma unroll
    for (int j = 0; j < 4; j++)
        cidx[j] = (wn * 32 + j * 8 + (lane >> 2)) ^ (kl << 3);

    // ---- hoisted epilogue params (cols fixed per thread) ----
    float2 bias1[4], scl[4], off[4];
    #pragma unroll
    for (int j = 0; j < 4; j++) {
        int c = wn * 32 + j * 8 + 2 * (lane & 3);
        bias1[j] = *(const float2*)(b1g + c);
        float2 b2v = *(const float2*)(b2g + c);
        float2 gm  = *(const float2*)(gamma + c);
        float2 bt  = *(const float2*)(beta + c);
        float2 rm  = *(const float2*)(rmean + c);
        float2 rv  = *(const float2*)(rvar + c);
        scl[j].x = gm.x * rsqrtf(rv.x + BN_EPS);
        scl[j].y = gm.y * rsqrtf(rv.y + BN_EPS);
        off[j].x = bt.x - rm.x * scl[j].x + b2v.x * scl[j].x;
        off[j].y = bt.y - rm.y * scl[j].y + b2v.y * scl[j].y;
    }

    const unsigned* sW1u = (const unsigned*)sW1;
    const unsigned* sW2u = (const unsigned*)sW2;

    int p = 0;
    for (int tile = blockIdx.x; tile < NTILES; tile += MLP_GRID, p ^= 1) {
        int nxt = tile + MLP_GRID;
        if (nxt < NTILES) {
            int row0n = nxt * TILE_M;
            const float4* src = (const float4*)agg + (size_t)row0n * 32;
            unsigned dst = base + 131072 + (p ^ 1) * 32768;
            for (int i = t; i < 2048; i += MLP_THREADS) {
                int row = i >> 5, c4 = i & 31;
                int dchunk = (i & ~31) | (c4 ^ (row & 7));
                bool ok = (row0n + row) < Nn;
                cpa16(dst + dchunk * 16, ok ? (src + i) : (const float4*)agg, ok);
            }
            cpa_commit();
            asm volatile("cp.async.wait_group 1;" ::: "memory");
        } else {
            asm volatile("cp.async.wait_group 0;" ::: "memory");
        }
        __syncthreads();

        float* sH = p ? sT1 : sT0;
        const unsigned* sHu = (const unsigned*)sH;
        int row0 = tile * TILE_M;

        float acc[4][4];
        #pragma unroll
        for (int j = 0; j < 4; j++)
            #pragma unroll
            for (int c = 0; c < 4; c++) acc[j][c] = 0.f;

        // ---- GEMM1: M = relu(H @ W1 + b1) ----
        #pragma unroll
        for (int ks = 0; ks < 16; ks++) {
            int k0 = ks * 8;
            int c1 = (k0 | acl) ^ s1;
            unsigned a0 = sHu[arO + c1],        a1 = sHu[arO8 + c1];
            unsigned a2 = sHu[arO + (c1 ^ 4)],  a3 = sHu[arO8 + (c1 ^ 4)];
            int krow = (k0 + kl) * 128;
            #pragma unroll
            for (int j = 0; j < 4; j++) {
                unsigned b0 = sW1u[krow + cidx[j]];
                unsigned b1 = sW1u[krow + 512 + cidx[j]];
                mma_tf32(acc[j][0], acc[j][1], acc[j][2], acc[j][3],
                         a0, a1, a2, a3, b0, b1);
            }
        }
        __syncthreads();   // all A reads done before in-place overwrite
        #pragma unroll
        for (int j = 0; j < 4; j++) {
            int c = wn * 32 + j * 8 + 2 * (lane & 3);
            unsigned v0 = f2tf32(fmaxf(acc[j][0] + bias1[j].x, 0.f));
            unsigned v1 = f2tf32(fmaxf(acc[j][1] + bias1[j].y, 0.f));
            unsigned v2 = f2tf32(fmaxf(acc[j][2] + bias1[j].x, 0.f));
            unsigned v3 = f2tf32(fmaxf(acc[j][3] + bias1[j].y, 0.f));
            int o = arO + (c ^ s1);
            ((uint2*)sH)[o >> 1]          = make_uint2(v0, v1);
            ((uint2*)sH)[(o + 1024) >> 1] = make_uint2(v2, v3);
        }
        __syncthreads();

        // ---- GEMM2 + BN + ReLU ----
        #pragma unroll
        for (int j = 0; j < 4; j++)
            #pragma unroll
            for (int c = 0; c < 4; c++) acc[j][c] = 0.f;

        #pragma unroll
        for (int ks = 0; ks < 16; ks++) {
            int k0 = ks * 8;
            int c1 = (k0 | acl) ^ s1;
            unsigned a0 = sHu[arO + c1],        a1 = sHu[arO8 + c1];
            unsigned a2 = sHu[arO + (c1 ^ 4)],  a3 = sHu[arO8 + (c1 ^ 4)];
            int krow = (k0 + kl) * 128;
            #pragma unroll
            for (int j = 0; j < 4; j++) {
                unsigned b0 = sW2u[krow + cidx[j]];
                unsigned b1 = sW2u[krow + 512 + cidx[j]];
                mma_tf32(acc[j][0], acc[j][1], acc[j][2], acc[j][3],
                         a0, a1, a2, a3, b0, b1);
            }
        }
        {
            int r0 = row0 + ar;
            int r8 = r0 + 8;
            #pragma unroll
            for (int j = 0; j < 4; j++) {
                int c = wn * 32 + j * 8 + 2 * (lane & 3);
                if (r0 < Nn) {
                    float2 v;
                    v.x = fmaxf(fmaf(acc[j][0], scl[j].x, off[j].x), 0.f);
                    v.y = fmaxf(fmaf(acc[j][1], scl[j].y, off[j].y), 0.f);
                    *(float2*)(xout + (size_t)r0 * 128 + c) = v;
                }
                if (r8 < Nn) {
                    float2 v;
                    v.x = fmaxf(fmaf(acc[j][2], scl[j].x, off[j].x), 0.f);
                    v.y = fmaxf(fmaf(acc[j][3], scl[j].y, off[j].y), 0.f);
                    *(float2*)(xout + (size_t)r8 * 128 + c) = v;
                }
            }
        }
        __syncthreads();   // buf p fully read before next prefetch reuses it
    }
}

// ---------------------------------------------------------------------------
__global__ void zero_pool_kernel(float* __restrict__ pool, float* __restrict__ cnt) {
    int i = blockIdx.x * blockDim.x + threadIdx.x;
    if (i < Gg * Ff) pool[i] = 0.f;
    if (i < Gg) cnt[i] = 0.f;
}

__global__ void pool_kernel(const float* __restrict__ x,
                            const int* __restrict__ batch,
                            float* __restrict__ pool, float* __restrict__ cnt) {
    int gid  = blockIdx.x * blockDim.x + threadIdx.x;
    int node = gid >> 5;
    int lane = gid & 31;
    if (node >= Nn) return;
    int g = batch[node];
    float4 v = *(const float4*)(x + (size_t)node * Ff + lane * 4);
    float* p = pool + g * Ff + lane * 4;
    asm volatile("red.global.add.v4.f32 [%0], {%1,%2,%3,%4};"
                 :: "l"(p), "f"(v.x), "f"(v.y), "f"(v.z), "f"(v.w) : "memory");
    if (lane == 0) atomicAdd(&cnt[g], 1.0f);
}

// ---------------------------------------------------------------------------
__global__ void final_kernel(const float* __restrict__ pool, const float* __restrict__ cnt,
                             const float* __restrict__ fc_w, const float* __restrict__ fc_b,
                             float* __restrict__ out) {
    int g = threadIdx.x;
    if (g >= Gg) return;
    float inv = 1.0f / fmaxf(cnt[g], 1.0f);
    float logits[Cc];
    #pragma unroll
    for (int j = 0; j < Cc; j++) logits[j] = fc_b[j];
    for (int k = 0; k < Ff; k++) {
        float p = pool[g * Ff + k] * inv;
        #pragma unroll
        for (int j = 0; j < Cc; j++) logits[j] += p * fc_w[k * Cc + j];
    }
    float m = logits[0];
    #pragma unroll
    for (int j = 1; j < Cc; j++) m = fmaxf(m, logits[j]);
    float s = 0.f;
    #pragma unroll
    for (int j = 0; j < Cc; j++) s += expf(logits[j] - m);
    float ls = logf(s) + m;
    #pragma unroll
    for (int j = 0; j < Cc; j++) out[g * Cc + j] = logits[j] - ls;
}

// ---------------------------------------------------------------------------
extern "C" void kernel_launch(void* const* d_in, const int* in_sizes, int n_in,
                              void* d_out, int out_size) {
    const float* x     = (const float*)d_in[0];
    const int*   ei    = (const int*)d_in[1];
    const int*   batch = (const int*)d_in[2];
    const float* W1    = (const float*)d_in[3];
    const float* b1    = (const float*)d_in[4];
    const float* W2    = (const float*)d_in[5];
    const float* b2    = (const float*)d_in[6];
    const float* gamma = (const float*)d_in[7];
    const float* beta  = (const float*)d_in[8];
    const float* rmean = (const float*)d_in[9];
    const float* rvar  = (const float*)d_in[10];
    const float* fc_w  = (const float*)d_in[11];
    const float* fc_b  = (const float*)d_in[12];
    float* out = (float*)d_out;

    cudaFuncSetAttribute(mlp_kernel, cudaFuncAttributeMaxDynamicSharedMemorySize, MLP_SMEM);

    float *agg, *x1, *x2, *pool, *cnt;
    int *deg, *rowptr, *cursor, *srcs;
    cudaGetSymbolAddress((void**)&agg,    g_agg);
    cudaGetSymbolAddress((void**)&x1,     g_x1);
    cudaGetSymbolAddress((void**)&x2,     g_x2);
    cudaGetSymbolAddress((void**)&pool,   g_pool);
    cudaGetSymbolAddress((void**)&cnt,    g_cnt);
    cudaGetSymbolAddress((void**)&deg,    g_deg);
    cudaGetSymbolAddress((void**)&rowptr, g_rowptr);
    cudaGetSymbolAddress((void**)&cursor, g_cursor);
    cudaGetSymbolAddress((void**)&srcs,   g_srcs);

    const int gather_blocks = (Nn * 32 + 255) / 256;
    const int pool_blocks   = (Nn * 32 + 255) / 256;

    // build CSR (dst-sorted) once per launch
    zero_deg_kernel<<<(Nn + 255) / 256, 256>>>(deg);
    count_kernel<<<(Ee + 255) / 256, 256>>>(ei, deg);
    scan_kernel<<<1, 1024>>>(deg, rowptr, cursor);
    fill_kernel<<<(Ee + 255) / 256, 256>>>(ei, cursor, srcs);

    const float* cur = x;
    float* outs[Ll] = { x1, x2, x1 };
    for (int l = 0; l < Ll; l++) {
        gather_kernel<<<gather_blocks, 256>>>(cur, rowptr, srcs, agg);
        mlp_kernel<<<MLP_GRID, MLP_THREADS, MLP_SMEM>>>(
            agg,
            W1 + (size_t)l * 128 * 128, b1 + (size_t)l * 128,
            W2 + (size_t)l * 128 * 128, b2 + (size_t)l * 128,
            gamma + (size_t)l * 128, beta + (size_t)l * 128,
            rmean + (size_t)l * 128, rvar + (size_t)l * 128,
            outs[l]);
        cur = outs[l];
    }

    zero_pool_kernel<<<(Gg * Ff + 255) / 256, 256>>>(pool, cnt);
    pool_kernel<<<pool_blocks, 256>>>(cur, batch, pool, cnt);
    final_kernel<<<1, 128>>>(pool, cnt, fc_w, fc_b, out);
}